// round 3
// baseline (speedup 1.0000x reference)
#include <cuda_runtime.h>
#include <cuda_bf16.h>
#include <cstdint>

#define NMAX 100000
#define EMAX 1000000

// ---------------- scratch ----------------
__device__ int   g_deg[NMAX];
__device__ int   g_rowptr[NMAX + 1];
__device__ int   g_cursor[NMAX];
__device__ float g_invdeg[NMAX];
__device__ int   g_eidx[EMAX];
__device__ float g_mean1[(size_t)NMAX * 64];
__device__ float g_h[(size_t)NMAX * 64];
__device__ float g_hn[(size_t)NMAX * 32];

// ---------------- helpers ----------------
__device__ __forceinline__ uint32_t f2tf32(float f) {
    uint32_t r;
    asm("cvt.rna.tf32.f32 %0, %1;" : "=r"(r) : "f"(f));
    return r;
}

__device__ __forceinline__ void mma_tf32(float c[4], uint32_t a0, uint32_t a1,
                                         uint32_t a2, uint32_t a3,
                                         uint32_t b0, uint32_t b1) {
    asm volatile(
        "mma.sync.aligned.m16n8k8.row.col.f32.tf32.tf32.f32 "
        "{%0,%1,%2,%3}, {%4,%5,%6,%7}, {%8,%9}, {%0,%1,%2,%3};"
        : "+f"(c[0]), "+f"(c[1]), "+f"(c[2]), "+f"(c[3])
        : "r"(a0), "r"(a1), "r"(a2), "r"(a3), "r"(b0), "r"(b1));
}

// ---------------- CSR build ----------------
__global__ void k_zero_deg(int n) {
    int i = blockIdx.x * blockDim.x + threadIdx.x;
    if (i < n) g_deg[i] = 0;
}

__global__ void k_count(const int* __restrict__ dst, int e) {
    int i = blockIdx.x * blockDim.x + threadIdx.x;
    if (i < e) atomicAdd(&g_deg[dst[i]], 1);
}

// single-block chunked exclusive scan over degrees
__global__ void __launch_bounds__(1024) k_scan(int n, int e) {
    __shared__ int s[1024];
    int tid = threadIdx.x;
    int C = (n + 1023) >> 10;
    int lo = tid * C;
    int hi = lo + C; if (hi > n) hi = n;
    int sum = 0;
    for (int i = lo; i < hi; i++) sum += g_deg[i];
    s[tid] = sum;
    __syncthreads();
#pragma unroll
    for (int off = 1; off < 1024; off <<= 1) {
        int t = (tid >= off) ? s[tid - off] : 0;
        __syncthreads();
        s[tid] += t;
        __syncthreads();
    }
    int run = s[tid] - sum;
    for (int i = lo; i < hi; i++) {
        g_rowptr[i] = run;
        g_cursor[i] = run;
        int d = g_deg[i];
        g_invdeg[i] = 1.0f / (float)(d > 1 ? d : 1);
        run += d;
    }
    if (tid == 0) g_rowptr[n] = e;
}

__global__ void k_scatter(const int* __restrict__ src, const int* __restrict__ dst, int e) {
    int i = blockIdx.x * blockDim.x + threadIdx.x;
    if (i < e) {
        int d = dst[i];
        int p = atomicAdd(&g_cursor[d], 1);
        g_eidx[p] = src[i];
    }
}

// ---------------- layer-1 aggregation (64-d mean of in-neighbors) ----------------
__global__ void k_agg1(const float* __restrict__ x, int n) {
    int warp = (blockIdx.x * blockDim.x + threadIdx.x) >> 5;
    int lane = threadIdx.x & 31;
    if (warp >= n) return;
    int start = g_rowptr[warp], end = g_rowptr[warp + 1];
    const float2* x2 = (const float2*)x;
    float ax = 0.f, ay = 0.f;
    int e = start;
    for (; e + 4 <= end; e += 4) {
        int s0 = g_eidx[e], s1 = g_eidx[e + 1], s2 = g_eidx[e + 2], s3 = g_eidx[e + 3];
        float2 a = x2[(size_t)s0 * 32 + lane];
        float2 b = x2[(size_t)s1 * 32 + lane];
        float2 c = x2[(size_t)s2 * 32 + lane];
        float2 d = x2[(size_t)s3 * 32 + lane];
        ax += (a.x + b.x) + (c.x + d.x);
        ay += (a.y + b.y) + (c.y + d.y);
    }
    for (; e < end; e++) {
        int s = g_eidx[e];
        float2 a = x2[(size_t)s * 32 + lane];
        ax += a.x; ay += a.y;
    }
    float id = g_invdeg[warp];
    float2 o; o.x = ax * id; o.y = ay * id;
    ((float2*)g_mean1)[(size_t)warp * 32 + lane] = o;
}

// ---------------- layer-1 GEMM (mma.sync tf32): h = relu([x|mean1]@[Ws1;Wn1] + b1)
// block: 256 thr (8 warps) x 128-row M tile. warp = 16 rows x 64 cols.
#define LDA1 132
#define LDB1 72
static constexpr int SM1 = (128 * LDA1 + 128 * LDB1) * 4;

__global__ void __launch_bounds__(256) k_mma1(
    const float* __restrict__ x, const float* __restrict__ ws,
    const float* __restrict__ wn, const float* __restrict__ bias, int n)
{
    extern __shared__ float sm[];
    float* As = sm;                 // [128][LDA1]
    float* Bs = sm + 128 * LDA1;    // [128][LDB1]  (k-major)
    int tid = threadIdx.x, wid = tid >> 5, lane = tid & 31;
    int n0 = blockIdx.x * 128;

    // A fill: row r (node n0+r), 128 K-floats = 32 float4
    for (int idx = tid; idx < 4096; idx += 256) {
        int r = idx >> 5, q = idx & 31;
        int node = n0 + r;
        float4 v = make_float4(0.f, 0.f, 0.f, 0.f);
        if (node < n) {
            v = (q < 16) ? ((const float4*)x)[(size_t)node * 16 + q]
                         : ((const float4*)g_mean1)[(size_t)node * 16 + (q - 16)];
        }
        float4 o;
        o.x = __uint_as_float(f2tf32(v.x));
        o.y = __uint_as_float(f2tf32(v.y));
        o.z = __uint_as_float(f2tf32(v.z));
        o.w = __uint_as_float(f2tf32(v.w));
        *(float4*)&As[r * LDA1 + q * 4] = o;
    }
    // B fill: Bs[k][nn] = Wcat[k][nn], k in [0,128), nn in [0,64)
    for (int idx = tid; idx < 8192; idx += 256) {
        int k = idx >> 6, nn = idx & 63;
        float v = (k < 64) ? ws[k * 64 + nn] : wn[(k - 64) * 64 + nn];
        Bs[k * LDB1 + nn] = __uint_as_float(f2tf32(v));
    }
    __syncthreads();

    int g = lane >> 2, t = lane & 3;
    float c[8][4];
#pragma unroll
    for (int i = 0; i < 8; i++) { c[i][0] = c[i][1] = c[i][2] = c[i][3] = 0.f; }

    const float* A0 = As + (wid * 16 + g) * LDA1;
    const float* A1 = A0 + 8 * LDA1;

#pragma unroll
    for (int ks = 0; ks < 16; ks++) {
        int k0 = ks * 8;
        uint32_t a0 = __float_as_uint(A0[k0 + t]);
        uint32_t a1 = __float_as_uint(A1[k0 + t]);
        uint32_t a2 = __float_as_uint(A0[k0 + t + 4]);
        uint32_t a3 = __float_as_uint(A1[k0 + t + 4]);
        const float* B0 = Bs + (k0 + t) * LDB1 + g;
        const float* B1 = Bs + (k0 + t + 4) * LDB1 + g;
#pragma unroll
        for (int nt = 0; nt < 8; nt++) {
            uint32_t b0 = __float_as_uint(B0[nt * 8]);
            uint32_t b1 = __float_as_uint(B1[nt * 8]);
            mma_tf32(c[nt], a0, a1, a2, a3, b0, b1);
        }
    }

    // epilogue: +bias, relu, store
    int r0 = n0 + wid * 16 + g;
    int r1 = r0 + 8;
#pragma unroll
    for (int nt = 0; nt < 8; nt++) {
        int col = nt * 8 + 2 * t;
        float b0 = __ldg(&bias[col]);
        float b1 = __ldg(&bias[col + 1]);
        if (r0 < n) {
            float2 o;
            o.x = fmaxf(c[nt][0] + b0, 0.f);
            o.y = fmaxf(c[nt][1] + b1, 0.f);
            *(float2*)&g_h[(size_t)r0 * 64 + col] = o;
        }
        if (r1 < n) {
            float2 o;
            o.x = fmaxf(c[nt][2] + b0, 0.f);
            o.y = fmaxf(c[nt][3] + b1, 0.f);
            *(float2*)&g_h[(size_t)r1 * 64 + col] = o;
        }
    }
}

// ---------------- layer-2 GEMM (mma.sync tf32): [out|hn] = h @ [Ws2|Wn2]
#define LDA2 68
#define LDB2 72
static constexpr int SM2 = (128 * LDA2 + 64 * LDB2) * 4;

__global__ void __launch_bounds__(256) k_mma2(
    const float* __restrict__ ws, const float* __restrict__ wn,
    const float* __restrict__ bias, float* __restrict__ out, int n)
{
    extern __shared__ float sm[];
    float* As = sm;                // [128][LDA2]
    float* Bs = sm + 128 * LDA2;   // [64][LDB2]
    int tid = threadIdx.x, wid = tid >> 5, lane = tid & 31;
    int n0 = blockIdx.x * 128;

    for (int idx = tid; idx < 2048; idx += 256) {
        int r = idx >> 4, q = idx & 15;
        int node = n0 + r;
        float4 v = make_float4(0.f, 0.f, 0.f, 0.f);
        if (node < n) v = ((const float4*)g_h)[(size_t)node * 16 + q];
        float4 o;
        o.x = __uint_as_float(f2tf32(v.x));
        o.y = __uint_as_float(f2tf32(v.y));
        o.z = __uint_as_float(f2tf32(v.z));
        o.w = __uint_as_float(f2tf32(v.w));
        *(float4*)&As[r * LDA2 + q * 4] = o;
    }
    for (int idx = tid; idx < 4096; idx += 256) {
        int k = idx >> 6, nn = idx & 63;
        float v = (nn < 32) ? ws[k * 32 + nn] : wn[k * 32 + (nn - 32)];
        Bs[k * LDB2 + nn] = __uint_as_float(f2tf32(v));
    }
    __syncthreads();

    int g = lane >> 2, t = lane & 3;
    float c[8][4];
#pragma unroll
    for (int i = 0; i < 8; i++) { c[i][0] = c[i][1] = c[i][2] = c[i][3] = 0.f; }

    const float* A0 = As + (wid * 16 + g) * LDA2;
    const float* A1 = A0 + 8 * LDA2;

#pragma unroll
    for (int ks = 0; ks < 8; ks++) {
        int k0 = ks * 8;
        uint32_t a0 = __float_as_uint(A0[k0 + t]);
        uint32_t a1 = __float_as_uint(A1[k0 + t]);
        uint32_t a2 = __float_as_uint(A0[k0 + t + 4]);
        uint32_t a3 = __float_as_uint(A1[k0 + t + 4]);
        const float* B0 = Bs + (k0 + t) * LDB2 + g;
        const float* B1 = Bs + (k0 + t + 4) * LDB2 + g;
#pragma unroll
        for (int nt = 0; nt < 8; nt++) {
            uint32_t b0 = __float_as_uint(B0[nt * 8]);
            uint32_t b1 = __float_as_uint(B1[nt * 8]);
            mma_tf32(c[nt], a0, a1, a2, a3, b0, b1);
        }
    }

    int r0 = n0 + wid * 16 + g;
    int r1 = r0 + 8;
#pragma unroll
    for (int nt = 0; nt < 4; nt++) {   // cols 0..31 -> out (+bias)
        int col = nt * 8 + 2 * t;
        float b0 = __ldg(&bias[col]);
        float b1 = __ldg(&bias[col + 1]);
        if (r0 < n) {
            float2 o; o.x = c[nt][0] + b0; o.y = c[nt][1] + b1;
            *(float2*)&out[(size_t)r0 * 32 + col] = o;
        }
        if (r1 < n) {
            float2 o; o.x = c[nt][2] + b0; o.y = c[nt][3] + b1;
            *(float2*)&out[(size_t)r1 * 32 + col] = o;
        }
    }
#pragma unroll
    for (int nt = 4; nt < 8; nt++) {   // cols 32..63 -> hn
        int col = (nt - 4) * 8 + 2 * t;
        if (r0 < n) {
            float2 o; o.x = c[nt][0]; o.y = c[nt][1];
            *(float2*)&g_hn[(size_t)r0 * 32 + col] = o;
        }
        if (r1 < n) {
            float2 o; o.x = c[nt][2]; o.y = c[nt][3];
            *(float2*)&g_hn[(size_t)r1 * 32 + col] = o;
        }
    }
}

// ---------------- layer-2 aggregation: out += invdeg * sum(hn[src]) ----------------
__global__ void k_agg2(float* __restrict__ out, int n) {
    int warp = (blockIdx.x * blockDim.x + threadIdx.x) >> 5;
    int lane = threadIdx.x & 31;
    if (warp >= n) return;
    int start = g_rowptr[warp], end = g_rowptr[warp + 1];
    float acc = 0.f;
    int e = start;
    for (; e + 4 <= end; e += 4) {
        int s0 = g_eidx[e], s1 = g_eidx[e + 1], s2 = g_eidx[e + 2], s3 = g_eidx[e + 3];
        float a = g_hn[(size_t)s0 * 32 + lane];
        float b = g_hn[(size_t)s1 * 32 + lane];
        float c = g_hn[(size_t)s2 * 32 + lane];
        float d = g_hn[(size_t)s3 * 32 + lane];
        acc += (a + b) + (c + d);
    }
    for (; e < end; e++) {
        int s = g_eidx[e];
        acc += g_hn[(size_t)s * 32 + lane];
    }
    out[(size_t)warp * 32 + lane] += acc * g_invdeg[warp];
}

// ---------------- launcher ----------------
extern "C" void kernel_launch(void* const* d_in, const int* in_sizes, int n_in,
                              void* d_out, int out_size) {
    const float* x   = (const float*)d_in[0];
    const int*   src = (const int*)d_in[1];
    const int*   dst = (const int*)d_in[2];
    const float* ws1 = (const float*)d_in[3];
    const float* wn1 = (const float*)d_in[4];
    const float* b1  = (const float*)d_in[5];
    const float* ws2 = (const float*)d_in[6];
    const float* wn2 = (const float*)d_in[7];
    const float* b2  = (const float*)d_in[8];
    float* out = (float*)d_out;

    int N = in_sizes[0] / 64;
    int E = in_sizes[1];
    int tiles = (N + 127) >> 7;

    cudaFuncSetAttribute(k_mma1, cudaFuncAttributeMaxDynamicSharedMemorySize, SM1);
    cudaFuncSetAttribute(k_mma2, cudaFuncAttributeMaxDynamicSharedMemorySize, SM2);

    // CSR build
    k_zero_deg<<<(N + 255) / 256, 256>>>(N);
    k_count<<<(E + 255) / 256, 256>>>(dst, E);
    k_scan<<<1, 1024>>>(N, E);
    k_scatter<<<(E + 255) / 256, 256>>>(src, dst, E);

    // layer 1
    k_agg1<<<(N + 7) / 8, 256>>>(x, N);
    k_mma1<<<tiles, 256, SM1>>>(x, ws1, wn1, b1, N);

    // layer 2
    k_mma2<<<tiles, 256, SM2>>>(ws2, wn2, b2, out, N);
    k_agg2<<<(N + 7) / 8, 256>>>(out, N);
}